// round 2
// baseline (speedup 1.0000x reference)
#include <cuda_runtime.h>

// Problem constants
#define CI 4
#define CO 8
#define TT_ 8
#define DD 96
#define HH 96
#define WW 96
#define EPS 1e-5f

// Conv tiling
#define TILE_D 4
#define TILE_H 8
#define TILE_W 16
#define HALO_D (TILE_D + 2)          // 6
#define HALO_H (TILE_H + 2)          // 10
#define HALO_W (TILE_W + 2)          // 18
#define IN_SLICE (HALO_D * HALO_H * HALO_W)   // 1080
#define IN_SMEM (CI * 3 * IN_SLICE)           // 12960 floats
#define W_SMEM (CI * 81 * CO)                 // 2592 floats
#define SMEM_BYTES ((IN_SMEM + W_SMEM) * 4)   // 62208 bytes
#define NTHREADS 128
#define PTS 4                                  // 128 * 4 = 512 = TILE_D*TILE_H*TILE_W

// Stats scratch (deterministic two-stage reduction; no float atomics)
__device__ float g_partial_sum[32][12];
__device__ float g_partial_sq[32][12];
__device__ float g_mean[32];
__device__ float g_rstd[32];

// ---------------------------------------------------------------------------
// Kernel 1: partial sums per (slice, d-chunk). slice = c*8 + t (contiguous
// 96^3 blocks of x). 12 chunks of 8 d-planes each.
// ---------------------------------------------------------------------------
__global__ void stats_partial(const float* __restrict__ x) {
    const int s = blockIdx.x;      // 0..31
    const int chunk = blockIdx.y;  // 0..11
    const float4* b4 = (const float4*)(x + (size_t)s * (DD * HH * WW)
                                         + (size_t)chunk * 8 * HH * WW);
    const int n4 = (8 * HH * WW) / 4;  // 18432
    float sum = 0.f, sq = 0.f;
    for (int i = threadIdx.x; i < n4; i += blockDim.x) {
        float4 v = b4[i];
        sum += v.x + v.y + v.z + v.w;
        sq  += v.x * v.x + v.y * v.y + v.z * v.z + v.w * v.w;
    }
    __shared__ float ssum[8], ssq[8];
    #pragma unroll
    for (int off = 16; off > 0; off >>= 1) {
        sum += __shfl_down_sync(0xffffffffu, sum, off);
        sq  += __shfl_down_sync(0xffffffffu, sq, off);
    }
    const int warp = threadIdx.x >> 5, lane = threadIdx.x & 31;
    if (lane == 0) { ssum[warp] = sum; ssq[warp] = sq; }
    __syncthreads();
    if (threadIdx.x == 0) {
        float ts = 0.f, tq = 0.f;
        #pragma unroll
        for (int w = 0; w < 8; w++) { ts += ssum[w]; tq += ssq[w]; }
        g_partial_sum[s][chunk] = ts;
        g_partial_sq[s][chunk]  = tq;
    }
}

// ---------------------------------------------------------------------------
// Kernel 2: finalize mean / rstd per slice (biased variance, as in jnp.var)
// ---------------------------------------------------------------------------
__global__ void stats_final() {
    const int s = threadIdx.x;  // 0..31
    float sum = 0.f, sq = 0.f;
    #pragma unroll
    for (int i = 0; i < 12; i++) { sum += g_partial_sum[s][i]; sq += g_partial_sq[s][i]; }
    const float inv = 1.0f / (float)(DD * HH * WW);
    const float mean = sum * inv;
    const float var = sq * inv - mean * mean;
    g_mean[s] = mean;
    g_rstd[s] = rsqrtf(var + EPS);
}

// ---------------------------------------------------------------------------
// Kernel 3: fused norm+ReLU (applied on smem fill) + direct 4D conv + bias.
// Block = 128 threads; each thread owns one (h,w) within the tile and a
// d-column of PTS=4 output points, for all 8 C_out -> 32 fp32 accumulators.
// ---------------------------------------------------------------------------
__global__ __launch_bounds__(NTHREADS)
void conv4d(const float* __restrict__ x, const float* __restrict__ wgt,
            const float* __restrict__ bias, float* __restrict__ out) {
    extern __shared__ float smem[];
    float* in_s = smem;                 // IN_SMEM floats
    float* w_s  = smem + IN_SMEM;       // W_SMEM floats

    const int t = blockIdx.y;           // 0..7
    int tile = blockIdx.x;              // 0..1727  (6 wtiles * 12 htiles * 24 dtiles)
    const int wt = tile % 6;  tile /= 6;
    const int ht = tile % 12; tile /= 12;
    const int dt = tile;                // 0..23
    const int d0 = dt * TILE_D, h0 = ht * TILE_H, w0 = wt * TILE_W;

    // --- load + repack weights: w_s[(cin*81 + tap)*8 + co] ---
    for (int i = threadIdx.x; i < W_SMEM; i += NTHREADS) {
        const int co  = i & 7;
        const int r   = i >> 3;             // cin*81 + tap
        const int cin = r / 81, tap = r % 81;
        w_s[i] = wgt[(co * CI + cin) * 81 + tap];
    }

    // --- load input halo with fused InstanceNorm + ReLU; zero-pad edges ---
    for (int i = threadIdx.x; i < IN_SMEM; i += NTHREADS) {
        const int lw = i % HALO_W;
        int r = i / HALO_W;
        const int lh = r % HALO_H; r /= HALO_H;
        const int ld = r % HALO_D; r /= HALO_D;
        const int ctt = r;                  // cin*3 + tt
        const int tt  = ctt % 3;
        const int cin = ctt / 3;
        const int gt = t + tt - 1;
        const int gd = d0 + ld - 1, gh = h0 + lh - 1, gw = w0 + lw - 1;
        float v = 0.f;
        if (gt >= 0 && gt < TT_ && gd >= 0 && gd < DD &&
            gh >= 0 && gh < HH && gw >= 0 && gw < WW) {
            const int s = cin * TT_ + gt;
            const float xv = x[((size_t)s * DD + gd) * (HH * WW) + gh * WW + gw];
            v = fmaxf(0.f, (xv - g_mean[s]) * g_rstd[s]);
        }
        in_s[i] = v;
    }
    __syncthreads();

    const int lh = (threadIdx.x >> 4) & 7;   // 0..7
    const int lw = threadIdx.x & 15;         // 0..15

    float acc[PTS][CO];
    #pragma unroll
    for (int p = 0; p < PTS; p++)
        #pragma unroll
        for (int c = 0; c < CO; c++) acc[p][c] = 0.f;

    #pragma unroll 1
    for (int ctt = 0; ctt < CI * 3; ctt++) {       // cin*3 + tt
        const float* ibase = in_s + ctt * IN_SLICE;
        const float* wbase = w_s + ctt * 27 * 8;   // cin*81 + tt*27 == 27*ctt
        #pragma unroll 1
        for (int kd = 0; kd < 3; kd++) {
            #pragma unroll
            for (int kh = 0; kh < 3; kh++) {
                #pragma unroll
                for (int kw = 0; kw < 3; kw++) {
                    const float* wp = wbase + ((kd * 3 + kh) * 3 + kw) * 8;
                    float wv[CO];
                    #pragma unroll
                    for (int c = 0; c < CO; c++) wv[c] = wp[c];
                    #pragma unroll
                    for (int p = 0; p < PTS; p++) {
                        const float iv = ibase[(p + kd) * (HALO_H * HALO_W)
                                               + (lh + kh) * HALO_W + (lw + kw)];
                        #pragma unroll
                        for (int c = 0; c < CO; c++)
                            acc[p][c] = fmaf(iv, wv[c], acc[p][c]);
                    }
                }
            }
        }
    }

    // --- write out, add bias ---
    #pragma unroll
    for (int c = 0; c < CO; c++) {
        const float bv = bias[c];
        #pragma unroll
        for (int p = 0; p < PTS; p++) {
            const int gd = d0 + p, gh = h0 + lh, gw = w0 + lw;
            out[(((size_t)c * TT_ + t) * DD + gd) * (HH * WW) + gh * WW + gw]
                = acc[p][c] + bv;
        }
    }
}

// ---------------------------------------------------------------------------
extern "C" void kernel_launch(void* const* d_in, const int* in_sizes, int n_in,
                              void* d_out, int out_size) {
    const float* x = (const float*)d_in[0];
    const float* w = (const float*)d_in[1];
    const float* b = (const float*)d_in[2];
    float* out = (float*)d_out;

    cudaFuncSetAttribute(conv4d, cudaFuncAttributeMaxDynamicSharedMemorySize,
                         SMEM_BYTES);

    stats_partial<<<dim3(32, 12), 256>>>(x);
    stats_final<<<1, 32>>>();
    conv4d<<<dim3(24 * 12 * 6, TT_), NTHREADS, SMEM_BYTES>>>(x, w, b, out);
}

// round 3
// speedup vs baseline: 1.0729x; 1.0729x over previous
#include <cuda_runtime.h>

// Problem constants
#define CI 4
#define CO 8
#define TT_ 8
#define DD 96
#define HH 96
#define WW 96
#define EPS 1e-5f

// Conv tiling
#define TILE_D 4
#define TILE_H 8
#define TILE_W 16
#define HALO_D (TILE_D + 2)          // 6
#define HALO_H (TILE_H + 2)          // 10
#define HALO_W (TILE_W + 2)          // 18
#define IN_SLICE (HALO_D * HALO_H * HALO_W)   // 1080
#define IN_SMEM (CI * 3 * IN_SLICE)           // 12960 floats
#define W_SMEM (CI * 81 * CO)                 // 2592 floats
#define SMEM_BYTES ((IN_SMEM + W_SMEM) * 4)   // 62208 bytes
#define NTHREADS 128
#define PTS 4                                  // 128 * 4 = 512 = TILE_D*TILE_H*TILE_W
#define NCHUNK 24

// Stats scratch (deterministic two-stage reduction; no float atomics)
__device__ float g_partial_sum[32][NCHUNK];
__device__ float g_partial_sq[32][NCHUNK];
__device__ float g_mean[32];
__device__ float g_rstd[32];

// ---- packed f32x2 helpers (SASS FFMA2 path; only reachable via PTX) ----
__device__ __forceinline__ unsigned long long pack2(float a, float b) {
    unsigned long long r;
    asm("mov.b64 %0, {%1, %2};" : "=l"(r) : "f"(a), "f"(b));
    return r;
}
__device__ __forceinline__ void fma2(unsigned long long& d,
                                     unsigned long long a, unsigned long long b) {
    asm("fma.rn.f32x2 %0, %1, %2, %0;" : "+l"(d) : "l"(a), "l"(b));
}
__device__ __forceinline__ void unpack2(unsigned long long v, float& lo, float& hi) {
    asm("mov.b64 {%0, %1}, %2;" : "=f"(lo), "=f"(hi) : "l"(v));
}

// ---------------------------------------------------------------------------
// Kernel 1: partial sums per (slice, d-chunk). slice = c*8 + t (contiguous
// 96^3 blocks of x). NCHUNK chunks of 4 d-planes each.
// ---------------------------------------------------------------------------
__global__ void stats_partial(const float* __restrict__ x) {
    const int s = blockIdx.x;      // 0..31
    const int chunk = blockIdx.y;  // 0..NCHUNK-1
    const float4* b4 = (const float4*)(x + (size_t)s * (DD * HH * WW)
                                         + (size_t)chunk * 4 * HH * WW);
    const int n4 = (4 * HH * WW) / 4;  // 9216
    float sum = 0.f, sq = 0.f;
    for (int i = threadIdx.x; i < n4; i += blockDim.x) {
        float4 v = b4[i];
        sum += v.x + v.y + v.z + v.w;
        sq  += v.x * v.x + v.y * v.y + v.z * v.z + v.w * v.w;
    }
    __shared__ float ssum[8], ssq[8];
    #pragma unroll
    for (int off = 16; off > 0; off >>= 1) {
        sum += __shfl_down_sync(0xffffffffu, sum, off);
        sq  += __shfl_down_sync(0xffffffffu, sq, off);
    }
    const int warp = threadIdx.x >> 5, lane = threadIdx.x & 31;
    if (lane == 0) { ssum[warp] = sum; ssq[warp] = sq; }
    __syncthreads();
    if (threadIdx.x == 0) {
        float ts = 0.f, tq = 0.f;
        #pragma unroll
        for (int w = 0; w < 8; w++) { ts += ssum[w]; tq += ssq[w]; }
        g_partial_sum[s][chunk] = ts;
        g_partial_sq[s][chunk]  = tq;
    }
}

// ---------------------------------------------------------------------------
// Kernel 2: finalize mean / rstd per slice (biased variance)
// ---------------------------------------------------------------------------
__global__ void stats_final() {
    const int s = threadIdx.x;  // 0..31
    float sum = 0.f, sq = 0.f;
    #pragma unroll
    for (int i = 0; i < NCHUNK; i++) { sum += g_partial_sum[s][i]; sq += g_partial_sq[s][i]; }
    const float inv = 1.0f / (float)(DD * HH * WW);
    const float mean = sum * inv;
    const float var = sq * inv - mean * mean;
    g_mean[s] = mean;
    g_rstd[s] = rsqrtf(var + EPS);
}

// ---------------------------------------------------------------------------
// Kernel 3: fused norm+ReLU (on smem fill) + direct 4D conv + bias.
// 128 threads; each thread owns one (h,w), a d-column of 4 points, all 8
// C_out as 16 packed f32x2 accumulators -> fma.rn.f32x2 (FFMA2).
// ---------------------------------------------------------------------------
__global__ __launch_bounds__(NTHREADS)
void conv4d(const float* __restrict__ x, const float* __restrict__ wgt,
            const float* __restrict__ bias, float* __restrict__ out) {
    extern __shared__ float smem[];
    float* in_s = smem;                 // IN_SMEM floats
    float* w_s  = smem + IN_SMEM;       // W_SMEM floats (8-byte aligned)

    const int t = blockIdx.y;           // 0..7
    int tile = blockIdx.x;              // 0..1727
    const int wt = tile % 6;  tile /= 6;
    const int ht = tile % 12; tile /= 12;
    const int dt = tile;                // 0..23
    const int d0 = dt * TILE_D, h0 = ht * TILE_H, w0 = wt * TILE_W;

    // --- load + repack weights: w_s[(ctt*27 + ktap)*8 + co] ---
    for (int i = threadIdx.x; i < W_SMEM; i += NTHREADS) {
        const int co  = i & 7;
        const int r   = i >> 3;             // cin*81 + tap
        const int cin = r / 81, tap = r % 81;
        w_s[i] = wgt[(co * CI + cin) * 81 + tap];
    }

    // --- load input halo with fused InstanceNorm + ReLU; zero-pad edges ---
    for (int i = threadIdx.x; i < IN_SMEM; i += NTHREADS) {
        const int lw = i % HALO_W;
        int r = i / HALO_W;
        const int lh = r % HALO_H; r /= HALO_H;
        const int ld = r % HALO_D; r /= HALO_D;
        const int ctt = r;                  // cin*3 + tt
        const int tt  = ctt % 3;
        const int cin = ctt / 3;
        const int gt = t + tt - 1;
        const int gd = d0 + ld - 1, gh = h0 + lh - 1, gw = w0 + lw - 1;
        float v = 0.f;
        if (gt >= 0 && gt < TT_ && gd >= 0 && gd < DD &&
            gh >= 0 && gh < HH && gw >= 0 && gw < WW) {
            const int s = cin * TT_ + gt;
            const float xv = x[((size_t)s * DD + gd) * (HH * WW) + gh * WW + gw];
            v = fmaxf(0.f, (xv - g_mean[s]) * g_rstd[s]);
        }
        in_s[i] = v;
    }
    __syncthreads();

    const int lh = (threadIdx.x >> 4) & 7;   // 0..7
    const int lw = threadIdx.x & 15;         // 0..15

    unsigned long long acc[PTS][4];          // [p][co_pair] packed f32x2
    #pragma unroll
    for (int p = 0; p < PTS; p++)
        #pragma unroll
        for (int cp = 0; cp < 4; cp++) acc[p][cp] = 0ull;

    #pragma unroll 1
    for (int ctt = 0; ctt < CI * 3; ctt++) {       // cin*3 + tt
        // all tap addresses become LDS [R+imm]
        const float* ib = in_s + ctt * IN_SLICE + lh * HALO_W + lw;
        const unsigned long long* wb =
            (const unsigned long long*)(w_s + ctt * 27 * 8);
        #pragma unroll
        for (int kd = 0; kd < 3; kd++) {
            #pragma unroll
            for (int kh = 0; kh < 3; kh++) {
                #pragma unroll
                for (int kw = 0; kw < 3; kw++) {
                    const int ktap = (kd * 3 + kh) * 3 + kw;
                    unsigned long long wv[4];
                    #pragma unroll
                    for (int cp = 0; cp < 4; cp++) wv[cp] = wb[ktap * 4 + cp];
                    #pragma unroll
                    for (int p = 0; p < PTS; p++) {
                        const float iv = ib[(p + kd) * (HALO_H * HALO_W)
                                            + kh * HALO_W + kw];
                        const unsigned long long iv2 = pack2(iv, iv);
                        #pragma unroll
                        for (int cp = 0; cp < 4; cp++)
                            fma2(acc[p][cp], iv2, wv[cp]);
                    }
                }
            }
        }
    }

    // --- write out, add bias ---
    #pragma unroll
    for (int cp = 0; cp < 4; cp++) {
        const float b0 = bias[2 * cp], b1 = bias[2 * cp + 1];
        #pragma unroll
        for (int p = 0; p < PTS; p++) {
            float lo, hi;
            unpack2(acc[p][cp], lo, hi);
            const int gd = d0 + p, gh = h0 + lh, gw = w0 + lw;
            const size_t sp = ((size_t)gd) * (HH * WW) + gh * WW + gw;
            out[(((size_t)(2 * cp) * TT_ + t) * DD) * (HH * WW) + sp] = lo + b0;
            out[(((size_t)(2 * cp + 1) * TT_ + t) * DD) * (HH * WW) + sp] = hi + b1;
        }
    }
}

// ---------------------------------------------------------------------------
extern "C" void kernel_launch(void* const* d_in, const int* in_sizes, int n_in,
                              void* d_out, int out_size) {
    const float* x = (const float*)d_in[0];
    const float* w = (const float*)d_in[1];
    const float* b = (const float*)d_in[2];
    float* out = (float*)d_out;

    cudaFuncSetAttribute(conv4d, cudaFuncAttributeMaxDynamicSharedMemorySize,
                         SMEM_BYTES);

    stats_partial<<<dim3(32, NCHUNK), 256>>>(x);
    stats_final<<<1, 32>>>();
    conv4d<<<dim3(24 * 12 * 6, TT_), NTHREADS, SMEM_BYTES>>>(x, w, b, out);
}

// round 6
// speedup vs baseline: 2.6991x; 2.5158x over previous
#include <cuda_runtime.h>
#include <cstdint>

// ---------------- problem constants ----------------
#define CI 4
#define CO 8
#define TT_ 8
#define DD 96
#define HH 96
#define WW 96
#define EPS 1e-5f
#define PLANE ((size_t)DD * HH * WW)

// ---------------- stats ----------------
#define NCHUNK 24
__device__ float g_partial_sum[32][NCHUNK];
__device__ float g_partial_sq[32][NCHUNK];
__device__ float g_mean[32];
__device__ float g_rstd[32];

__global__ void stats_partial(const float* __restrict__ x) {
    const int s = blockIdx.x, chunk = blockIdx.y;
    const float4* b4 = (const float4*)(x + (size_t)s * PLANE + (size_t)chunk * 4 * HH * WW);
    const int n4 = (4 * HH * WW) / 4;
    float sum = 0.f, sq = 0.f;
    for (int i = threadIdx.x; i < n4; i += blockDim.x) {
        float4 v = b4[i];
        sum += v.x + v.y + v.z + v.w;
        sq  += v.x * v.x + v.y * v.y + v.z * v.z + v.w * v.w;
    }
    __shared__ float ssum[8], ssq[8];
    #pragma unroll
    for (int off = 16; off > 0; off >>= 1) {
        sum += __shfl_down_sync(0xffffffffu, sum, off);
        sq  += __shfl_down_sync(0xffffffffu, sq, off);
    }
    const int warp = threadIdx.x >> 5, lane = threadIdx.x & 31;
    if (lane == 0) { ssum[warp] = sum; ssq[warp] = sq; }
    __syncthreads();
    if (threadIdx.x == 0) {
        float ts = 0.f, tq = 0.f;
        #pragma unroll
        for (int w = 0; w < 8; w++) { ts += ssum[w]; tq += ssq[w]; }
        g_partial_sum[s][chunk] = ts;
        g_partial_sq[s][chunk]  = tq;
    }
}

__global__ void stats_final() {
    const int s = threadIdx.x;
    float sum = 0.f, sq = 0.f;
    #pragma unroll
    for (int i = 0; i < NCHUNK; i++) { sum += g_partial_sum[s][i]; sq += g_partial_sq[s][i]; }
    const float inv = 1.0f / (float)PLANE;
    const float mean = sum * inv;
    const float var = sq * inv - mean * mean;
    g_mean[s] = mean;
    g_rstd[s] = rsqrtf(var + EPS);
}

// ---------------- mma helpers (baseline PTX, no "a"-features) ----------------
__device__ __forceinline__ uint32_t smem_u32(const void* p) {
    uint32_t a;
    asm("{ .reg .u64 t; cvta.to.shared.u64 t, %1; cvt.u32.u64 %0, t; }" : "=r"(a) : "l"(p));
    return a;
}
__device__ __forceinline__ uint32_t f2tf32(float f) {
    uint32_t r;
    asm("cvt.rna.tf32.f32 %0, %1;" : "=r"(r) : "f"(f));
    return r;
}
__device__ __forceinline__ void ldsm4(uint32_t& a0, uint32_t& a1, uint32_t& a2,
                                      uint32_t& a3, uint32_t addr) {
    asm volatile("ldmatrix.sync.aligned.m8n8.x4.shared.b16 {%0,%1,%2,%3}, [%4];"
                 : "=r"(a0), "=r"(a1), "=r"(a2), "=r"(a3) : "r"(addr));
}
__device__ __forceinline__ void mma_tf32(float* d, uint32_t a0, uint32_t a1,
                                         uint32_t a2, uint32_t a3,
                                         uint32_t b0, uint32_t b1) {
    asm volatile(
        "mma.sync.aligned.m16n8k8.row.col.f32.tf32.tf32.f32 "
        "{%0,%1,%2,%3}, {%4,%5,%6,%7}, {%8,%9}, {%0,%1,%2,%3};"
        : "+f"(d[0]), "+f"(d[1]), "+f"(d[2]), "+f"(d[3])
        : "r"(a0), "r"(a1), "r"(a2), "r"(a3), "r"(b0), "r"(b1));
}

// ---------------- conv kernel config ----------------
#define D_TILE 4
#define H_TILE 4
#define DL 6                       // D_TILE + 2
#define HL 6                       // H_TILE + 2
#define NROWS (DL * HL)            // 36 rows per phase
#define ROW_CHUNKS 100             // w' = -1..98, 16B each (zero-padded ends)
#define ROWB (ROW_CHUNKS * 16)     // 1600 B
#define IN_BYTES (NROWS * ROWB)    // 57600
#define B_OFF IN_BYTES             // weight fragments after input slice
#define B_BYTES (9 * 2 * 32 * 8)   // 4608 (per-phase: 9 taps, 2 k-slices, 32 lanes, 8B)
#define SMEM_TOTAL (IN_BYTES + B_BYTES)   // 62208
#define NTH 256

__global__ __launch_bounds__(NTH, 2)
void conv4d_mma(const float* __restrict__ x, const float* __restrict__ wgt,
                const float* __restrict__ bias, float* __restrict__ out) {
    extern __shared__ char smem[];
    const uint32_t sbase = smem_u32(smem);
    const int tid = threadIdx.x;
    const int wid = tid >> 5, lane = tid & 31;

    const int bh = blockIdx.x % 24, bd = blockIdx.x / 24;   // 24 x 24 tiles
    const int t = blockIdx.y;
    const int d0 = bd * D_TILE, h0 = bh * H_TILE;

    // ldmatrix per-lane static offset: sub0 rows m=0..7, sub1 m=8..15,
    // sub2 = +16B (w+1 window), sub3 = rows 8..15 +16B
    const int msub = lane & 7, quad = lane >> 3;
    const uint32_t lane_off = (uint32_t)(msub * 16 + (quad & 1) * 128 + (quad >> 1) * 16);

    // accumulators: 2 (od,oh) pairs x 6 w-chunks x 4 regs
    float acc[2][6][4];
    #pragma unroll
    for (int p = 0; p < 2; p++)
        #pragma unroll
        for (int w = 0; w < 6; w++)
            #pragma unroll
            for (int r = 0; r < 4; r++) acc[p][w][r] = 0.f;

    #pragma unroll 1
    for (int tt = 0; tt < 3; tt++) {
        const int tp = t + tt - 1;
        if (tp < 0 || tp >= TT_) continue;      // uniform across CTA

        __syncthreads();   // previous phase fully consumed before overwrite

        float mean[CI], rstd[CI];
        #pragma unroll
        for (int ci = 0; ci < CI; ci++) {
            mean[ci] = g_mean[ci * TT_ + tp];
            rstd[ci] = g_rstd[ci * TT_ + tp];
        }

        // ---- load input slice: [dl 6][hl 6][chunk 100][ci 4] tf32, norm+ReLU+pad
        for (int i = tid; i < NROWS * ROW_CHUNKS; i += NTH) {
            const int row = i / ROW_CHUNKS;
            const int p = i - row * ROW_CHUNKS;
            const int wp = p - 1;
            const int dl = row / HL, hl = row - dl * HL;
            const int dp = d0 - 1 + dl, hp = h0 - 1 + hl;
            uint4 v = make_uint4(0u, 0u, 0u, 0u);
            if (((unsigned)wp < WW) & ((unsigned)dp < DD) & ((unsigned)hp < HH)) {
                const size_t sp = ((size_t)dp * HH + hp) * WW + wp;
                const float* xb = x + (size_t)tp * PLANE + sp;
                v.x = f2tf32(fmaxf(0.f, (xb[0]          - mean[0]) * rstd[0]));
                v.y = f2tf32(fmaxf(0.f, (xb[8 * PLANE]  - mean[1]) * rstd[1]));
                v.z = f2tf32(fmaxf(0.f, (xb[16 * PLANE] - mean[2]) * rstd[2]));
                v.w = f2tf32(fmaxf(0.f, (xb[24 * PLANE] - mean[3]) * rstd[3]));
            }
            *(uint4*)(smem + row * ROWB + p * 16) = v;
        }

        // ---- build B fragments for this tt: [kdkh 9][j 2][lane 32][b0,b1]
        for (int i = tid; i < B_BYTES / 4; i += NTH) {   // 1152 u32
            const int which = i & 1;
            const int l = (i >> 1) & 31;
            const int j = (i >> 6) & 1;
            const int kdkh = i >> 7;
            const int kd = kdkh / 3, kh = kdkh % 3;
            const int kl = (l & 3) + which * 4;          // k within slice
            const int kwg = j * 2 + (kl >> 2);           // global kw 0..3
            const int ci = kl & 3, co = l >> 2;
            uint32_t v = 0u;
            if (kwg < 3)
                v = f2tf32(wgt[(co * CI + ci) * 81 + tt * 27 + kd * 9 + kh * 3 + kwg]);
            *(uint32_t*)(smem + B_OFF + i * 4) = v;
        }
        __syncthreads();

        // ---- compute: each warp owns 2 (od,oh) pairs x 6 w-chunks ----
        #pragma unroll
        for (int pp = 0; pp < 2; pp++) {
            const int pid = wid * 2 + pp;
            const int od = pid >> 2, oh = pid & 3;

            // preload the 9x2 B fragments (36 regs)
            uint2 bf[9][2];
            const uint2* bsm = (const uint2*)(smem + B_OFF);
            #pragma unroll
            for (int tp9 = 0; tp9 < 9; tp9++)
                #pragma unroll
                for (int j = 0; j < 2; j++)
                    bf[tp9][j] = bsm[(tp9 * 2 + j) * 32 + lane];

            #pragma unroll
            for (int wc = 0; wc < 6; wc++) {
                const uint32_t wbase = sbase + lane_off + wc * 256;
                #pragma unroll
                for (int kd = 0; kd < 3; kd++) {
                    #pragma unroll
                    for (int kh = 0; kh < 3; kh++) {
                        const uint32_t raddr =
                            wbase + ((od + kd) * HL + (oh + kh)) * ROWB;
                        uint32_t a0, a1, a2, a3;
                        ldsm4(a0, a1, a2, a3, raddr);
                        mma_tf32(acc[pp][wc], a0, a1, a2, a3,
                                 bf[kd * 3 + kh][0].x, bf[kd * 3 + kh][0].y);
                        ldsm4(a0, a1, a2, a3, raddr + 32);
                        mma_tf32(acc[pp][wc], a0, a1, a2, a3,
                                 bf[kd * 3 + kh][1].x, bf[kd * 3 + kh][1].y);
                    }
                }
            }
        }
    }

    // ---- epilogue: bias add + store ----
    const int co0 = (lane & 3) * 2;
    const float bv0 = bias[co0], bv1 = bias[co0 + 1];
    #pragma unroll
    for (int pp = 0; pp < 2; pp++) {
        const int pid = wid * 2 + pp;
        const int od = pid >> 2, oh = pid & 3;
        const int gd = d0 + od, gh = h0 + oh;
        #pragma unroll
        for (int wc = 0; wc < 6; wc++) {
            const int wa = wc * 16 + (lane >> 2);
            const size_t spA = (((size_t)t * DD + gd) * HH + gh) * WW + wa;
            out[(size_t)(co0    ) * (TT_ * PLANE) + spA] = acc[pp][wc][0] + bv0;
            out[(size_t)(co0 + 1) * (TT_ * PLANE) + spA] = acc[pp][wc][1] + bv1;
            out[(size_t)(co0    ) * (TT_ * PLANE) + spA + 8] = acc[pp][wc][2] + bv0;
            out[(size_t)(co0 + 1) * (TT_ * PLANE) + spA + 8] = acc[pp][wc][3] + bv1;
        }
    }
}

// ---------------------------------------------------------------------------
extern "C" void kernel_launch(void* const* d_in, const int* in_sizes, int n_in,
                              void* d_out, int out_size) {
    const float* x = (const float*)d_in[0];
    const float* w = (const float*)d_in[1];
    const float* b = (const float*)d_in[2];
    float* out = (float*)d_out;

    cudaFuncSetAttribute(conv4d_mma, cudaFuncAttributeMaxDynamicSharedMemorySize,
                         SMEM_TOTAL);

    stats_partial<<<dim3(32, NCHUNK), 256>>>(x);
    stats_final<<<1, 32>>>();
    conv4d_mma<<<dim3(24 * 24, TT_), NTH, SMEM_TOTAL>>>(x, w, b, out);
}